// round 7
// baseline (speedup 1.0000x reference)
#include <cuda_runtime.h>
#include <math.h>

#define TB 400
#define HH 512
#define VV 32000

__device__ float g_Xpre[2][12800u*2048];
__device__ float g_WT[4][HH*2048];      // 0 encf,1 encb,2 decWih,3 decWhh  [k][j]
__device__ float g_attT[2][HH*HH];
__device__ float g_genT[HH*VV];
__device__ float g_h[2][2][32*HH];
__device__ float g_mem[12800u*HH];
__device__ float g_dh[2][32*HH];
__device__ int   g_w[32];
__device__ float g_D[64*HH];
__device__ float g_Sc[12800u*64];
__device__ float g_Z[2048];
__device__ float g_V[64*HH];
__device__ float g_vts[64*32*HH];
__device__ float g_logits[32u*VV];
__device__ unsigned g_bc[2];

__device__ __forceinline__ float sigf(float x){ return 1.f/(1.f+expf(-x)); }

__device__ __forceinline__ void gbar(int w, unsigned nblk){
  __syncthreads();
  if (threadIdx.x==0){
    __threadfence();
    unsigned my = atomicAdd(&g_bc[w],1u);
    unsigned tgt = (my/nblk+1u)*nblk;
    while (*(volatile unsigned*)&g_bc[w] < tgt) {}
  }
  __syncthreads();
}

__global__ void k_prep(){
  size_t i=(size_t)blockIdx.x*256+threadIdx.x;
  if(i<12800u*HH) g_mem[i]=0.f;
  if(i<2u*2*32*HH) ((float*)g_h)[i]=0.f;
}

__global__ void k_tr(const float* __restrict__ W, float* __restrict__ Wt, int R, int C){
  __shared__ float t[32][33];
  int r0=blockIdx.x*32, c0=blockIdx.y*32, x=threadIdx.x, y=threadIdx.y;
  #pragma unroll
  for(int i=0;i<32;i+=8) t[y+i][x]=W[(size_t)(r0+y+i)*C+c0+x];
  __syncthreads();
  #pragma unroll
  for(int i=0;i<32;i+=8) Wt[(size_t)(c0+y+i)*R+r0+x]=t[x][y+i];
}

__global__ void k_xpre(const int* __restrict__ orig, const float* __restrict__ emb,
                       const float* __restrict__ Wf, const float* __restrict__ bf,
                       const float* __restrict__ Wb, const float* __restrict__ bb){
  __shared__ float As[16][68], Bs[16][68];
  __shared__ int tok[64];
  int dir=blockIdx.z;
  const float* W   = dir?Wb:Wf;
  const float* bias= dir?bb:bf;
  int m0=blockIdx.x*64, n0=blockIdx.y*64, tid=threadIdx.x;
  if(tid<64){ int m=m0+tid; tok[tid]=orig[(m&31)*TB+(m>>5)]; }
  __syncthreads();
  float acc[4][4];
  #pragma unroll
  for(int i=0;i<4;i++)
    #pragma unroll
    for(int j=0;j<4;j++) acc[i][j]=0.f;
  int tx=tid&15, ty=tid>>4, lm=tid>>2, lk=(tid&3)*4;
  for(int kb=0;kb<HH;kb+=16){
    float4 a=*(const float4*)(emb+(size_t)tok[lm]*HH+kb+lk);
    As[lk][lm]=a.x; As[lk+1][lm]=a.y; As[lk+2][lm]=a.z; As[lk+3][lm]=a.w;
    float4 bv=*(const float4*)(W+(size_t)(n0+lm)*HH+kb+lk);
    Bs[lk][lm]=bv.x; Bs[lk+1][lm]=bv.y; Bs[lk+2][lm]=bv.z; Bs[lk+3][lm]=bv.w;
    __syncthreads();
    #pragma unroll
    for(int k=0;k<16;k++){
      float af[4],bf4[4];
      #pragma unroll
      for(int i=0;i<4;i++) af[i]=As[k][ty+16*i];
      #pragma unroll
      for(int j=0;j<4;j++) bf4[j]=Bs[k][tx+16*j];
      #pragma unroll
      for(int i=0;i<4;i++)
        #pragma unroll
        for(int j=0;j<4;j++) acc[i][j]+=af[i]*bf4[j];
    }
    __syncthreads();
  }
  float* o=g_Xpre[dir];
  #pragma unroll
  for(int i=0;i<4;i++){ int m=m0+ty+16*i;
    #pragma unroll
    for(int j=0;j<4;j++){ int n=n0+tx+16*j;
      o[(size_t)m*2048+n]=acc[i][j]+bias[n]; } }
}

// persistent encoder: 128 blocks, loops t=0..399, software grid barrier
__global__ void __launch_bounds__(256,1) k_enc(){
  extern __shared__ float sm[];
  float* sh=sm; float* red=sm+16384;
  int blk=blockIdx.x, dir=blk>>6, tid=threadIdx.x;
  int cb=(blk&63)*8;
  int q=tid>>5, r=tid&31, gate=r>>3, col=cb+(r&7);
  int j=gate*HH+col, k0=q*64;
  float w[64];
  #pragma unroll
  for(int k=0;k<64;k++) w[k]=g_WT[dir][(size_t)(k0+k)*2048+j];
  int cl=tid>>5, b2=tid&31, c=cb+cl, hi=b2*HH+c;
  float cc=0.f;
  for(int t=0;t<TB;t++){
    int par=t&1, tt=dir?(TB-1-t):t;
    const float4* h4=(const float4*)g_h[dir][par];
    float4* s4=(float4*)sh;
    #pragma unroll
    for(int i=0;i<16;i++) s4[tid+i*256]=__ldcg(h4+tid+i*256);
    __syncthreads();
    float acc[32];
    #pragma unroll
    for(int b=0;b<32;b++) acc[b]=0.f;
    #pragma unroll 4
    for(int kk=0;kk<16;kk++){
      const float* hb=sh+k0+kk*4;
      #pragma unroll
      for(int b=0;b<32;b++){
        float4 h=*(const float4*)(hb+b*HH);
        acc[b]+=w[kk*4]*h.x+w[kk*4+1]*h.y+w[kk*4+2]*h.z+w[kk*4+3]*h.w;
      }
    }
    #pragma unroll
    for(int b=0;b<32;b++) red[(q*32+r)*33+b]=acc[b];
    __syncthreads();
    float gs[4];
    #pragma unroll
    for(int g=0;g<4;g++){ float s=0.f;
      #pragma unroll
      for(int qq=0;qq<8;qq++) s+=red[(qq*32+g*8+cl)*33+b2];
      gs[g]=s; }
    const float* xp=g_Xpre[dir]+((size_t)tt*32+b2)*2048;
    float i_=sigf(gs[0]+xp[c]), f_=sigf(gs[1]+xp[HH+c]);
    float gg=tanhf(gs[2]+xp[2*HH+c]), o_=sigf(gs[3]+xp[3*HH+c]);
    cc=f_*cc+i_*gg;
    float hn=o_*tanhf(cc);
    g_h[dir][1-par][hi]=hn;
    atomicAdd(&g_mem[((size_t)tt*32+b2)*HH+c],hn);
    gbar(0,128);
  }
}

__global__ void k_dinit(){
  int i=blockIdx.x*256+threadIdx.x;
  if(i<16384) g_dh[0][i]=g_h[0][0][i]+g_h[1][0][i];
  if(i<32) g_w[i]=1;
}

// persistent decoder: 148 blocks, loops s=0..63, 6 phases with barriers
__global__ void __launch_bounds__(256,1) k_dec(const float* __restrict__ emb,
    const float* __restrict__ db, const float* __restrict__ genb, float* __restrict__ out){
  extern __shared__ float sm[];
  float* sh=sm; float* xs=sm+16384; float* red=sm+32768;
  __shared__ float sAs[16][68], sBs[16][68], sZ[2048];
  __shared__ float smx[256], sms[256]; __shared__ int smi[256];
  __shared__ int tok[32];
  __shared__ float lseS;
  int blk=blockIdx.x, tid=threadIdx.x;
  float cc=0.f;
  for(int s=0;s<64;s++){
    int par=s&1;
    // -- phase 1: LSTM cell (blocks 0..63)
    if(blk<64){
      if(tid<32) tok[tid]=__ldcg(&g_w[tid]);
      const float4* h4=(const float4*)g_dh[par];
      float4* s4=(float4*)sh;
      #pragma unroll
      for(int i=0;i<16;i++) s4[tid+i*256]=__ldcg(h4+tid+i*256);
      __syncthreads();
      float4* x4=(float4*)xs;
      const float4* e4=(const float4*)emb;
      for(int i=tid;i<4096;i+=256) x4[i]=e4[(size_t)tok[i>>7]*128+(i&127)];
      __syncthreads();
      int q=tid>>5, r=tid&31, gate=r>>3, cb=blk*8, col=cb+(r&7);
      int j=gate*HH+col, k0=q*64;
      float acc[32];
      #pragma unroll
      for(int b=0;b<32;b++) acc[b]=0.f;
      for(int kk=0;kk<16;kk++){
        float wh[4],wi[4];
        #pragma unroll
        for(int i2=0;i2<4;i2++){ wh[i2]=g_WT[3][(size_t)(k0+kk*4+i2)*2048+j];
                                 wi[i2]=g_WT[2][(size_t)(k0+kk*4+i2)*2048+j]; }
        const float* hb=sh+k0+kk*4; const float* xb=xs+k0+kk*4;
        #pragma unroll
        for(int b=0;b<32;b++){
          float4 h=*(const float4*)(hb+b*HH); float4 x=*(const float4*)(xb+b*HH);
          acc[b]+=wh[0]*h.x+wh[1]*h.y+wh[2]*h.z+wh[3]*h.w
                 +wi[0]*x.x+wi[1]*x.y+wi[2]*x.z+wi[3]*x.w;
        }
      }
      #pragma unroll
      for(int b=0;b<32;b++) red[(q*32+r)*33+b]=acc[b];
      __syncthreads();
      int cl=tid>>5, b2=tid&31;
      float gs[4];
      #pragma unroll
      for(int g=0;g<4;g++){ float s2=0.f;
        #pragma unroll
        for(int qq=0;qq<8;qq++) s2+=red[(qq*32+g*8+cl)*33+b2];
        gs[g]=s2; }
      int c=cb+cl;
      float i_=sigf(gs[0]+db[c]), f_=sigf(gs[1]+db[HH+c]);
      float gg=tanhf(gs[2]+db[2*HH+c]), o_=sigf(gs[3]+db[3*HH+c]);
      cc=f_*cc+i_*gg;
      g_dh[1-par][b2*HH+c]=o_*tanhf(cc);
    }
    gbar(1,148);
    // -- phase 2: D = h @ attW^T (0..63) ; zero Z,V (64..147)
    if(blk<64){
      int bb=blk&31;
      sh[tid]    =__ldcg(&g_dh[1-par][bb*HH+tid]);
      sh[tid+256]=__ldcg(&g_dh[1-par][bb*HH+tid+256]);
      __syncthreads();
      const float* At=g_attT[blk>>5];
      float a0=0.f,a1=0.f;
      for(int k=0;k<HH;k++){ float h=sh[k];
        a0+=At[(size_t)k*HH+tid]*h; a1+=At[(size_t)k*HH+tid+256]*h; }
      g_D[blk*HH+tid]=a0; g_D[blk*HH+tid+256]=a1;
      __syncthreads();
    } else {
      for(int i=(blk-64)*256+tid;i<2048;i+=84*256) g_Z[i]=0.f;
      for(int i=(blk-64)*256+tid;i<32768;i+=84*256) g_V[i]=0.f;
    }
    gbar(1,148);
    // -- phase 3: scores Sc=exp(tanh(mem@D^T)) + Z
    {
      for(int i=tid;i<2048;i+=256) sZ[i]=0.f;
      __syncthreads();
      int tx=tid&15, ty=tid>>4, lm=tid>>2, lk=(tid&3)*4;
      for(int job=blk;job<200;job+=148){
        int m0=job*64;
        float acc[4][4];
        #pragma unroll
        for(int i=0;i<4;i++)
          #pragma unroll
          for(int j=0;j<4;j++) acc[i][j]=0.f;
        for(int kb=0;kb<HH;kb+=16){
          float4 a=*(const float4*)(g_mem+(size_t)(m0+lm)*HH+kb+lk);
          sAs[lk][lm]=a.x; sAs[lk+1][lm]=a.y; sAs[lk+2][lm]=a.z; sAs[lk+3][lm]=a.w;
          float4 bv=__ldcg((const float4*)(g_D+(size_t)lm*HH+kb+lk));
          sBs[lk][lm]=bv.x; sBs[lk+1][lm]=bv.y; sBs[lk+2][lm]=bv.z; sBs[lk+3][lm]=bv.w;
          __syncthreads();
          #pragma unroll
          for(int k=0;k<16;k++){
            float af[4],bf4[4];
            #pragma unroll
            for(int i=0;i<4;i++) af[i]=sAs[k][ty+16*i];
            #pragma unroll
            for(int j=0;j<4;j++) bf4[j]=sBs[k][tx+16*j];
            #pragma unroll
            for(int i=0;i<4;i++)
              #pragma unroll
              for(int j=0;j<4;j++) acc[i][j]+=af[i]*bf4[j];
          }
          __syncthreads();
        }
        #pragma unroll
        for(int i=0;i<4;i++){ int m=m0+ty+16*i;
          #pragma unroll
          for(int j=0;j<4;j++){ int bi=tx+16*j;
            float e=expf(tanhf(acc[i][j]));
            g_Sc[(size_t)m*64+bi]=e;
            atomicAdd(&sZ[bi*32+(m&31)],e);
          } }
      }
      __syncthreads();
      for(int i=tid;i<2048;i+=256) atomicAdd(&g_Z[i],sZ[i]);
    }
    gbar(1,148);
    // -- phase 4: V = beta^T @ mem
    {
      for(int i=tid;i<2048;i+=256) sZ[i]=1.f/__ldcg(&g_Z[i]);
      __syncthreads();
      int tx=tid&15, ty=tid>>4, c64=tid&63, kg=tid>>6;
      for(int job=blk;job<200;job+=148){
        int h0=(job&7)*64;
        size_t r0=(size_t)(job>>3)*512;
        float acc[4][4];
        #pragma unroll
        for(int i=0;i<4;i++)
          #pragma unroll
          for(int j=0;j<4;j++) acc[i][j]=0.f;
        for(int ch=0;ch<32;ch++){
          size_t rb=r0+ch*16;
          #pragma unroll
          for(int i=0;i<4;i++){
            int k=kg*4+i;
            sAs[k][c64]=__ldcg(&g_Sc[(rb+k)*64+c64])*sZ[c64*32+(int)((rb+k)&31)];
            sBs[k][c64]=g_mem[(rb+k)*HH+h0+c64];
          }
          __syncthreads();
          #pragma unroll
          for(int k=0;k<16;k++){
            float af[4],bf4[4];
            #pragma unroll
            for(int i=0;i<4;i++) af[i]=sAs[k][ty+16*i];
            #pragma unroll
            for(int j=0;j<4;j++) bf4[j]=sBs[k][tx+16*j];
            #pragma unroll
            for(int i=0;i<4;i++)
              #pragma unroll
              for(int j=0;j<4;j++) acc[i][j]+=af[i]*bf4[j];
          }
          __syncthreads();
        }
        #pragma unroll
        for(int i=0;i<4;i++)
          #pragma unroll
          for(int j=0;j<4;j++)
            atomicAdd(&g_V[(ty+16*i)*HH+h0+tx+16*j],acc[i][j]);
      }
    }
    gbar(1,148);
    // -- phase 5: logits (0..124) + vts copy (125)
    if(blk<125){
      float4* x4=(float4*)sh;
      #pragma unroll
      for(int i=0;i<16;i++) x4[tid+i*256]=__ldcg(((const float4*)g_V)+tid+i*256);
      __syncthreads();
      int v=blk*256+tid;
      float acc[32];
      #pragma unroll
      for(int b=0;b<32;b++) acc[b]=0.f;
      for(int k=0;k<HH;k+=4){
        float w0=g_genT[(size_t)(k+0)*VV+v];
        float w1=g_genT[(size_t)(k+1)*VV+v];
        float w2=g_genT[(size_t)(k+2)*VV+v];
        float w3=g_genT[(size_t)(k+3)*VV+v];
        #pragma unroll
        for(int b=0;b<32;b++){
          float4 x=*(const float4*)(sh+b*HH+k);
          acc[b]+=w0*x.x+w1*x.y+w2*x.z+w3*x.w;
        }
      }
      float bb2=genb[v];
      #pragma unroll
      for(int b=0;b<32;b++) g_logits[(size_t)b*VV+v]=acc[b]+bb2;
      __syncthreads();
    } else if(blk==125){
      for(int i=tid;i<16384;i+=256) g_vts[(size_t)s*16384+i]=__ldcg(&g_V[16384+i]);
    }
    gbar(1,148);
    // -- phase 6: log_softmax + argmax (0..31)
    if(blk<32){
      const float* lg=g_logits+(size_t)blk*VV;
      float m=-1e30f,sum=0.f; int idx=0;
      for(int v=tid;v<VV;v+=256){
        float l=__ldcg(&lg[v]);
        if(l>m){ sum=sum*expf(m-l)+1.f; m=l; idx=v; }
        else sum+=expf(l-m);
      }
      smx[tid]=m; sms[tid]=sum; smi[tid]=idx;
      __syncthreads();
      for(int o=128;o;o>>=1){
        if(tid<o){
          float m1=smx[tid],m2=smx[tid+o],s1=sms[tid],s2=sms[tid+o];
          int i1=smi[tid],i2=smi[tid+o];
          float M=fmaxf(m1,m2);
          sms[tid]=s1*expf(m1-M)+s2*expf(m2-M);
          smx[tid]=M;
          smi[tid]=(m2>m1)?i2:(m1>m2?i1:min(i1,i2));
        }
        __syncthreads();
      }
      if(tid==0){ lseS=smx[0]+logf(sms[0]); g_w[blk]=smi[0]; }
      __syncthreads();
      float L=lseS;
      float* ob=out+((size_t)blk*64+s)*VV;
      for(int v=tid;v<VV;v+=256) ob[v]=__ldcg(&lg[v])-L;
    }
    gbar(1,148);
  }
}

__global__ void k_cls(const float* __restrict__ W, const float* __restrict__ cb,
                      float* __restrict__ out){
  __shared__ float rr[256];
  int b=blockIdx.x, l=blockIdx.y, tid=threadIdx.x;
  const float* wr=W+(size_t)l*237568;
  float acc=0.f;
  for(int k=tid;k<32768;k+=256)
    acc+=wr[k]*g_vts[(size_t)(k>>9)*16384+b*HH+(k&511)];
  for(int k=32768+tid;k<237568;k+=256){
    int kk=k-32768;
    acc+=wr[k]*g_mem[((size_t)(kk>>9)*32+b)*HH+(kk&511)];
  }
  rr[tid]=acc;
  __syncthreads();
  for(int o=128;o;o>>=1){ if(tid<o) rr[tid]+=rr[tid+o]; __syncthreads(); }
  if(tid==0) out[65536000u+b*5+l]=rr[0]+cb[l];
}

extern "C" void kernel_launch(void* const* d_in, const int* in_sizes, int n_in,
                              void* d_out, int out_size){
  const int*   orig=(const int*)  d_in[0];
  const float* emb =(const float*)d_in[1];
  const float* eWif=(const float*)d_in[2];
  const float* eWhf=(const float*)d_in[3];
  const float* ebf =(const float*)d_in[4];
  const float* eWib=(const float*)d_in[5];
  const float* eWhb=(const float*)d_in[6];
  const float* ebb =(const float*)d_in[7];
  const float* dWi =(const float*)d_in[8];
  const float* dWh =(const float*)d_in[9];
  const float* db  =(const float*)d_in[10];
  const float* sAw =(const float*)d_in[11];
  const float* cAw =(const float*)d_in[12];
  const float* gW  =(const float*)d_in[13];
  const float* gb  =(const float*)d_in[14];
  const float* cW  =(const float*)d_in[15];
  const float* cb  =(const float*)d_in[16];
  float* out=(float*)d_out;

  cudaFuncSetAttribute(k_enc, cudaFuncAttributeMaxDynamicSharedMemorySize, 99328);
  cudaFuncSetAttribute(k_dec, cudaFuncAttributeMaxDynamicSharedMemorySize, 164864);

  float *pWT,*pAtt,*pGen;
  cudaGetSymbolAddress((void**)&pWT, g_WT);
  cudaGetSymbolAddress((void**)&pAtt,g_attT);
  cudaGetSymbolAddress((void**)&pGen,g_genT);

  k_prep<<<25600,256>>>();
  dim3 tb(32,8);
  k_tr<<<dim3(64,16),tb>>>(eWhf, pWT+0u*HH*2048, 2048, 512);
  k_tr<<<dim3(64,16),tb>>>(eWhb, pWT+1u*HH*2048, 2048, 512);
  k_tr<<<dim3(64,16),tb>>>(dWi,  pWT+2u*HH*2048, 2048, 512);
  k_tr<<<dim3(64,16),tb>>>(dWh,  pWT+3u*HH*2048, 2048, 512);
  k_tr<<<dim3(16,16),tb>>>(sAw,  pAtt+0u*HH*HH, 512, 512);
  k_tr<<<dim3(16,16),tb>>>(cAw,  pAtt+1u*HH*HH, 512, 512);
  k_tr<<<dim3(1000,16),tb>>>(gW, pGen, VV, 512);

  k_xpre<<<dim3(200,32,2),256>>>(orig, emb, eWif, ebf, eWib, ebb);
  k_enc<<<128,256,99328>>>();
  k_dinit<<<64,256>>>();
  k_dec<<<148,256,164864>>>(emb, db, gb, out);
  k_cls<<<dim3(32,5),256>>>(cW, cb, out);
}

// round 8
// speedup vs baseline: 1.0635x; 1.0635x over previous
#include <cuda_runtime.h>
#include <math.h>

#define TB 400
#define HH 512
#define VV 32000

__device__ float g_Xpre[2][12800u*2048];
__device__ float g_WT[4][HH*2048];      // 0 encf,1 encb,2 decWih,3 decWhh  [k][j]
__device__ float g_genT[HH*VV];
__device__ float g_h[2][2][32*HH];
__device__ float g_mem[12800u*HH];
__device__ float g_dh[2][32*HH];
__device__ int   g_w[32];
__device__ float g_lse[32];
__device__ float g_D[64*HH];
__device__ float g_Sc[12800u*64];
__device__ float g_Z[2048];
__device__ float g_V[64*HH];
__device__ float g_vts[64*32*HH];
__device__ float g_logits[32u*VV];
__device__ unsigned g_bc[4];

__device__ __forceinline__ float sigf(float x){ return 1.f/(1.f+expf(-x)); }

__device__ __forceinline__ void gbar(int w, unsigned nblk){
  __syncthreads();
  if (threadIdx.x==0){
    __threadfence();
    unsigned my = atomicAdd(&g_bc[w],1u);
    unsigned tgt = (my/nblk+1u)*nblk;
    while (*(volatile unsigned*)&g_bc[w] < tgt) {}
  }
  __syncthreads();
}

__global__ void k_prep(){
  size_t i=(size_t)blockIdx.x*256+threadIdx.x;
  if(i<12800u*HH) g_mem[i]=0.f;
  if(i<2u*2*32*HH) ((float*)g_h)[i]=0.f;
}

// all transposes in ONE launch (keeps k_dec as the 6th launch for ncu)
__global__ void k_tr_all(const float* __restrict__ eWhf, const float* __restrict__ eWhb,
                         const float* __restrict__ dWi, const float* __restrict__ dWh,
                         const float* __restrict__ gW){
  __shared__ float t[32][33];
  int blk=blockIdx.x;
  const float* W; float* Wt; int R,C,tIdx;
  if(blk<4096){
    int mat=blk>>10; tIdx=blk&1023; R=2048; C=512;
    W = mat==0?eWhf: mat==1?eWhb: mat==2?dWi:dWh;
    Wt = g_WT[mat];
  } else {
    tIdx=blk-4096; R=VV; C=512; W=gW; Wt=g_genT;
  }
  int r0=(tIdx>>4)*32, c0=(tIdx&15)*32;
  int x=threadIdx.x, y=threadIdx.y;
  #pragma unroll
  for(int i=0;i<32;i+=8) t[y+i][x]=W[(size_t)(r0+y+i)*C+c0+x];
  __syncthreads();
  #pragma unroll
  for(int i=0;i<32;i+=8) Wt[(size_t)(c0+y+i)*R+r0+x]=t[x][y+i];
}

__global__ void k_xpre(const int* __restrict__ orig, const float* __restrict__ emb,
                       const float* __restrict__ Wf, const float* __restrict__ bf,
                       const float* __restrict__ Wb, const float* __restrict__ bb){
  __shared__ float As[16][68], Bs[16][68];
  __shared__ int tok[64];
  int dir=blockIdx.z;
  const float* W   = dir?Wb:Wf;
  const float* bias= dir?bb:bf;
  int m0=blockIdx.x*64, n0=blockIdx.y*64, tid=threadIdx.x;
  if(tid<64){ int m=m0+tid; tok[tid]=orig[(m&31)*TB+(m>>5)]; }
  __syncthreads();
  float acc[4][4];
  #pragma unroll
  for(int i=0;i<4;i++)
    #pragma unroll
    for(int j=0;j<4;j++) acc[i][j]=0.f;
  int tx=tid&15, ty=tid>>4, lm=tid>>2, lk=(tid&3)*4;
  for(int kb=0;kb<HH;kb+=16){
    float4 a=*(const float4*)(emb+(size_t)tok[lm]*HH+kb+lk);
    As[lk][lm]=a.x; As[lk+1][lm]=a.y; As[lk+2][lm]=a.z; As[lk+3][lm]=a.w;
    float4 bv=*(const float4*)(W+(size_t)(n0+lm)*HH+kb+lk);
    Bs[lk][lm]=bv.x; Bs[lk+1][lm]=bv.y; Bs[lk+2][lm]=bv.z; Bs[lk+3][lm]=bv.w;
    __syncthreads();
    #pragma unroll
    for(int k=0;k<16;k++){
      float4 af=*(const float4*)&As[k][ty*4];
      float4 bf4=*(const float4*)&Bs[k][tx*4];
      float av[4]={af.x,af.y,af.z,af.w}, bv2[4]={bf4.x,bf4.y,bf4.z,bf4.w};
      #pragma unroll
      for(int i=0;i<4;i++)
        #pragma unroll
        for(int j=0;j<4;j++) acc[i][j]+=av[i]*bv2[j];
    }
    __syncthreads();
  }
  float* o=g_Xpre[dir];
  float4 bias4=*(const float4*)(bias+n0+tx*4);
  #pragma unroll
  for(int i=0;i<4;i++){
    int m=m0+ty*4+i;
    float4 r; r.x=acc[i][0]+bias4.x; r.y=acc[i][1]+bias4.y;
    r.z=acc[i][2]+bias4.z; r.w=acc[i][3]+bias4.w;
    *(float4*)(o+(size_t)m*2048+n0+tx*4)=r;
  }
}

// persistent encoder: 128 blocks (fwd 0-63 barrier[2], bwd 64-127 barrier[3])
__global__ void __launch_bounds__(256,1) k_enc(){
  extern __shared__ float sm[];
  float* sh=sm; float* red=sm+16384;
  __shared__ float xg[4][8][32];
  int blk=blockIdx.x, dir=blk>>6, tid=threadIdx.x;
  int cb=(blk&63)*8;
  int q=tid>>5, r=tid&31, gate=r>>3, col=cb+(r&7);
  int j=gate*HH+col, k0=q*64;
  float w[64];
  #pragma unroll
  for(int k=0;k<64;k++) w[k]=g_WT[dir][(size_t)(k0+k)*2048+j];
  int cl=tid>>5, b2=tid&31, c=cb+cl, hi=b2*HH+c;
  float cc=0.f;
  int bw = 2+dir;
  for(int t=0;t<TB;t++){
    int par=t&1, tt=dir?(TB-1-t):t;
    // stage Xpre gate values: xg[gate][cl][b]
    const float* xbase = g_Xpre[dir] + (size_t)tt*32*2048;
    #pragma unroll
    for(int p=0;p<4;p++){
      int idx=p*256+tid;
      int g=idx>>8, rem=idx&255, b=rem>>3, ccx=rem&7;
      xg[g][ccx][b] = xbase[(size_t)b*2048 + g*512 + cb + ccx];
    }
    const float4* h4=(const float4*)g_h[dir][par];
    float4* s4=(float4*)sh;
    #pragma unroll
    for(int i=0;i<16;i++) s4[tid+i*256]=__ldcg(h4+tid+i*256);
    __syncthreads();
    float acc[32];
    #pragma unroll
    for(int b=0;b<32;b++) acc[b]=0.f;
    #pragma unroll 4
    for(int kk=0;kk<16;kk++){
      const float* hb=sh+k0+kk*4;
      #pragma unroll
      for(int b=0;b<32;b++){
        float4 h=*(const float4*)(hb+b*HH);
        acc[b]+=w[kk*4]*h.x+w[kk*4+1]*h.y+w[kk*4+2]*h.z+w[kk*4+3]*h.w;
      }
    }
    #pragma unroll
    for(int b=0;b<32;b++) red[(q*32+r)*33+b]=acc[b];
    __syncthreads();
    float gs[4];
    #pragma unroll
    for(int g=0;g<4;g++){ float s=0.f;
      #pragma unroll
      for(int qq=0;qq<8;qq++) s+=red[(qq*32+g*8+cl)*33+b2];
      gs[g]=s; }
    float i_=sigf(gs[0]+xg[0][cl][b2]), f_=sigf(gs[1]+xg[1][cl][b2]);
    float gg=tanhf(gs[2]+xg[2][cl][b2]), o_=sigf(gs[3]+xg[3][cl][b2]);
    cc=f_*cc+i_*gg;
    float hn=o_*tanhf(cc);
    g_h[dir][1-par][hi]=hn;
    atomicAdd(&g_mem[((size_t)tt*32+b2)*HH+c],hn);
    gbar(bw,64);
  }
}

__global__ void k_dinit(){
  int i=blockIdx.x*256+threadIdx.x;
  if(i<16384) g_dh[0][i]=g_h[0][0][i]+g_h[1][0][i];
  if(i<32) g_w[i]=1;
}

// persistent decoder: 148 blocks
__global__ void __launch_bounds__(256,1) k_dec(const float* __restrict__ emb,
    const float* __restrict__ db, const float* __restrict__ genb,
    const float* __restrict__ sAw, const float* __restrict__ cAw,
    float* __restrict__ out){
  extern __shared__ float sm[];
  float* sh=sm; float* xs=sm+16384; float* red=sm+32768;
  __shared__ float sAs[16][68], sBs[16][68], sZ[2048];
  __shared__ float smx[256], sms[256]; __shared__ int smi[256];
  __shared__ int tok[32];
  int blk=blockIdx.x, tid=threadIdx.x;
  float cc=0.f;
  for(int s=0;s<64;s++){
    int par=s&1;
    // -- phase 1: LSTM cell (0..63) ; logits writeback of step s-1 (64..147)
    if(blk<64){
      if(tid<32) tok[tid]=__ldcg(&g_w[tid]);
      const float4* h4=(const float4*)g_dh[par];
      float4* s4=(float4*)sh;
      #pragma unroll
      for(int i=0;i<16;i++) s4[tid+i*256]=__ldcg(h4+tid+i*256);
      __syncthreads();
      float4* x4=(float4*)xs;
      const float4* e4=(const float4*)emb;
      for(int i=tid;i<4096;i+=256) x4[i]=e4[(size_t)tok[i>>7]*128+(i&127)];
      __syncthreads();
      int q=tid>>5, r=tid&31, gate=r>>3, cb=blk*8, col=cb+(r&7);
      int j=gate*HH+col, k0=q*64;
      float acc[32];
      #pragma unroll
      for(int b=0;b<32;b++) acc[b]=0.f;
      for(int kk=0;kk<16;kk++){
        float wh[4],wi[4];
        #pragma unroll
        for(int i2=0;i2<4;i2++){ wh[i2]=g_WT[3][(size_t)(k0+kk*4+i2)*2048+j];
                                 wi[i2]=g_WT[2][(size_t)(k0+kk*4+i2)*2048+j]; }
        const float* hb=sh+k0+kk*4; const float* xb=xs+k0+kk*4;
        #pragma unroll
        for(int b=0;b<32;b++){
          float4 h=*(const float4*)(hb+b*HH); float4 x=*(const float4*)(xb+b*HH);
          acc[b]+=wh[0]*h.x+wh[1]*h.y+wh[2]*h.z+wh[3]*h.w
                 +wi[0]*x.x+wi[1]*x.y+wi[2]*x.z+wi[3]*x.w;
        }
      }
      #pragma unroll
      for(int b=0;b<32;b++) red[(q*32+r)*33+b]=acc[b];
      __syncthreads();
      int cl=tid>>5, b2=tid&31;
      float gs[4];
      #pragma unroll
      for(int g=0;g<4;g++){ float s2=0.f;
        #pragma unroll
        for(int qq=0;qq<8;qq++) s2+=red[(qq*32+g*8+cl)*33+b2];
        gs[g]=s2; }
      int c=cb+cl;
      float i_=sigf(gs[0]+db[c]), f_=sigf(gs[1]+db[HH+c]);
      float gg=tanhf(gs[2]+db[2*HH+c]), o_=sigf(gs[3]+db[3*HH+c]);
      cc=f_*cc+i_*gg;
      g_dh[1-par][b2*HH+c]=o_*tanhf(cc);
    } else if(s>0){
      for(unsigned idx=(blk-64)*256+tid; idx<1024000u; idx+=84*256){
        unsigned b=idx/32000u, v=idx-b*32000u;
        out[((size_t)b*64+(s-1))*VV+v]=__ldcg(&g_logits[(size_t)b*VV+v])-__ldcg(&g_lse[b]);
      }
    }
    gbar(1,148);
    // -- phase 2: D = h @ attW^T (0..63, vectorized) ; zero Z,V (64..147)
    if(blk<64){
      int bb=blk&31;
      sh[tid]    =__ldcg(&g_dh[1-par][bb*HH+tid]);
      sh[tid+256]=__ldcg(&g_dh[1-par][bb*HH+tid+256]);
      __syncthreads();
      const float* At=(blk>>5)?cAw:sAw;
      const float4* h4=(const float4*)sh;
      float a0=0.f,a1=0.f;
      const float4* w0=(const float4*)(At+(size_t)tid*HH);
      const float4* w1=(const float4*)(At+(size_t)(tid+256)*HH);
      #pragma unroll 4
      for(int k=0;k<128;k++){
        float4 h=h4[k], u=w0[k], v=w1[k];
        a0+=u.x*h.x+u.y*h.y+u.z*h.z+u.w*h.w;
        a1+=v.x*h.x+v.y*h.y+v.z*h.z+v.w*h.w;
      }
      g_D[blk*HH+tid]=a0; g_D[blk*HH+tid+256]=a1;
      __syncthreads();
    } else {
      for(int i=(blk-64)*256+tid;i<2048;i+=84*256) g_Z[i]=0.f;
      for(int i=(blk-64)*256+tid;i<32768;i+=84*256) g_V[i]=0.f;
    }
    gbar(1,148);
    // -- phase 3: Sc = exp(tanh(mem@D^T)) + Z   (400 jobs of 32 rows)
    {
      for(int i=tid;i<2048;i+=256) sZ[i]=0.f;
      __syncthreads();
      float* A3=&sAs[0][0];  // stride 36
      int tx=tid&15, ty=tid>>4;
      int lmA=tid>>3, lkA=(tid&7)*2;
      int lmB=tid>>2, lkB=(tid&3)*4;
      for(int job=blk;job<400;job+=148){
        int m0=job*32;
        float acc[2][4];
        #pragma unroll
        for(int i=0;i<2;i++)
          #pragma unroll
          for(int j=0;j<4;j++) acc[i][j]=0.f;
        for(int kb=0;kb<HH;kb+=16){
          float2 a=*(const float2*)(g_mem+(size_t)(m0+lmA)*HH+kb+lkA);
          A3[lkA*36+lmA]=a.x; A3[(lkA+1)*36+lmA]=a.y;
          float4 bv=__ldcg((const float4*)(g_D+(size_t)lmB*HH+kb+lkB));
          sBs[lkB][lmB]=bv.x; sBs[lkB+1][lmB]=bv.y; sBs[lkB+2][lmB]=bv.z; sBs[lkB+3][lmB]=bv.w;
          __syncthreads();
          #pragma unroll
          for(int k=0;k<16;k++){
            float2 af=*(const float2*)&A3[k*36+ty*2];
            float4 bf4=*(const float4*)&sBs[k][tx*4];
            float av[2]={af.x,af.y}, bv2[4]={bf4.x,bf4.y,bf4.z,bf4.w};
            #pragma unroll
            for(int i=0;i<2;i++)
              #pragma unroll
              for(int j=0;j<4;j++) acc[i][j]+=av[i]*bv2[j];
          }
          __syncthreads();
        }
        #pragma unroll
        for(int i=0;i<2;i++){
          int m=m0+ty*2+i;
          float4 e;
          e.x=expf(tanhf(acc[i][0])); e.y=expf(tanhf(acc[i][1]));
          e.z=expf(tanhf(acc[i][2])); e.w=expf(tanhf(acc[i][3]));
          *(float4*)(g_Sc+(size_t)m*64+tx*4)=e;
          atomicAdd(&sZ[(tx*4+0)*32+(m&31)],e.x);
          atomicAdd(&sZ[(tx*4+1)*32+(m&31)],e.y);
          atomicAdd(&sZ[(tx*4+2)*32+(m&31)],e.z);
          atomicAdd(&sZ[(tx*4+3)*32+(m&31)],e.w);
        }
      }
      __syncthreads();
      for(int i=tid;i<2048;i+=256) atomicAdd(&g_Z[i],sZ[i]);
    }
    gbar(1,148);
    // -- phase 4: V = beta^T @ mem   (400 jobs: 8 h-tiles x 50 r-chunks of 256)
    {
      for(int i=tid;i<2048;i+=256) sZ[i]=1.f/__ldcg(&g_Z[i]);
      __syncthreads();
      int tx=tid&15, ty=tid>>4, c64=tid&63, kg=tid>>6;
      for(int job=blk;job<400;job+=148){
        int h0=(job&7)*64;
        size_t r0=(size_t)(job>>3)*256;
        float acc[4][4];
        #pragma unroll
        for(int i=0;i<4;i++)
          #pragma unroll
          for(int j=0;j<4;j++) acc[i][j]=0.f;
        for(int ch=0;ch<16;ch++){
          size_t rb=r0+ch*16;
          #pragma unroll
          for(int i=0;i<4;i++){
            int k=kg*4+i;
            sAs[k][c64]=__ldcg(&g_Sc[(rb+k)*64+c64])*sZ[c64*32+(int)((rb+k)&31)];
            sBs[k][c64]=g_mem[(rb+k)*HH+h0+c64];
          }
          __syncthreads();
          #pragma unroll
          for(int k=0;k<16;k++){
            float4 af=*(const float4*)&sAs[k][ty*4];
            float4 bf4=*(const float4*)&sBs[k][tx*4];
            float av[4]={af.x,af.y,af.z,af.w}, bv2[4]={bf4.x,bf4.y,bf4.z,bf4.w};
            #pragma unroll
            for(int i=0;i<4;i++)
              #pragma unroll
              for(int j=0;j<4;j++) acc[i][j]+=av[i]*bv2[j];
          }
          __syncthreads();
        }
        #pragma unroll
        for(int i=0;i<4;i++)
          #pragma unroll
          for(int j=0;j<4;j++)
            atomicAdd(&g_V[(ty*4+i)*HH+h0+tx*4+j],acc[i][j]);
      }
    }
    gbar(1,148);
    // -- phase 5: logits (0..124) + vts copy (125)
    if(blk<125){
      float4* x4=(float4*)sh;
      #pragma unroll
      for(int i=0;i<16;i++) x4[tid+i*256]=__ldcg(((const float4*)g_V)+tid+i*256);
      __syncthreads();
      int v=blk*256+tid;
      float acc[32];
      #pragma unroll
      for(int b=0;b<32;b++) acc[b]=0.f;
      for(int k=0;k<HH;k+=4){
        float w0=g_genT[(size_t)(k+0)*VV+v];
        float w1=g_genT[(size_t)(k+1)*VV+v];
        float w2=g_genT[(size_t)(k+2)*VV+v];
        float w3=g_genT[(size_t)(k+3)*VV+v];
        #pragma unroll
        for(int b=0;b<32;b++){
          float4 x=*(const float4*)(sh+b*HH+k);
          acc[b]+=w0*x.x+w1*x.y+w2*x.z+w3*x.w;
        }
      }
      float bb2=genb[v];
      #pragma unroll
      for(int b=0;b<32;b++) g_logits[(size_t)b*VV+v]=acc[b]+bb2;
      __syncthreads();
    } else if(blk==125){
      for(int i=tid;i<16384;i+=256) g_vts[(size_t)s*16384+i]=__ldcg(&g_V[16384+i]);
    }
    gbar(1,148);
    // -- phase 6: lse + argmax only (0..31)
    if(blk<32){
      const float* lg=g_logits+(size_t)blk*VV;
      float m=-1e30f,sum=0.f; int idx=0;
      for(int v=tid;v<VV;v+=256){
        float l=__ldcg(&lg[v]);
        if(l>m){ sum=sum*expf(m-l)+1.f; m=l; idx=v; }
        else sum+=expf(l-m);
      }
      smx[tid]=m; sms[tid]=sum; smi[tid]=idx;
      __syncthreads();
      for(int o=128;o;o>>=1){
        if(tid<o){
          float m1=smx[tid],m2=smx[tid+o],s1=sms[tid],s2=sms[tid+o];
          int i1=smi[tid],i2=smi[tid+o];
          float M=fmaxf(m1,m2);
          sms[tid]=s1*expf(m1-M)+s2*expf(m2-M);
          smx[tid]=M;
          smi[tid]=(m2>m1)?i2:(m1>m2?i1:min(i1,i2));
        }
        __syncthreads();
      }
      if(tid==0){ g_lse[blk]=smx[0]+logf(sms[0]); g_w[blk]=smi[0]; }
    }
    gbar(1,148);
  }
  // tail: writeback for s=63 (all blocks)
  for(unsigned idx=blk*256+tid; idx<1024000u; idx+=148*256){
    unsigned b=idx/32000u, v=idx-b*32000u;
    out[((size_t)b*64+63)*VV+v]=__ldcg(&g_logits[(size_t)b*VV+v])-__ldcg(&g_lse[b]);
  }
}

__global__ void k_cls(const float* __restrict__ W, const float* __restrict__ cb,
                      float* __restrict__ out){
  __shared__ float rr[256];
  int b=blockIdx.x, l=blockIdx.y, tid=threadIdx.x;
  const float* wr=W+(size_t)l*237568;
  float acc=0.f;
  for(int k=tid;k<32768;k+=256)
    acc+=wr[k]*g_vts[(size_t)(k>>9)*16384+b*HH+(k&511)];
  for(int k=32768+tid;k<237568;k+=256){
    int kk=k-32768;
    acc+=wr[k]*g_mem[((size_t)(kk>>9)*32+b)*HH+(kk&511)];
  }
  rr[tid]=acc;
  __syncthreads();
  for(int o=128;o;o>>=1){ if(tid<o) rr[tid]+=rr[tid+o]; __syncthreads(); }
  if(tid==0) out[65536000u+b*5+l]=rr[0]+cb[l];
}

extern "C" void kernel_launch(void* const* d_in, const int* in_sizes, int n_in,
                              void* d_out, int out_size){
  const int*   orig=(const int*)  d_in[0];
  const float* emb =(const float*)d_in[1];
  const float* eWif=(const float*)d_in[2];
  const float* eWhf=(const float*)d_in[3];
  const float* ebf =(const float*)d_in[4];
  const float* eWib=(const float*)d_in[5];
  const float* eWhb=(const float*)d_in[6];
  const float* ebb =(const float*)d_in[7];
  const float* dWi =(const float*)d_in[8];
  const float* dWh =(const float*)d_in[9];
  const float* db  =(const float*)d_in[10];
  const float* sAw =(const float*)d_in[11];
  const float* cAw =(const float*)d_in[12];
  const float* gW  =(const float*)d_in[13];
  const float* gb  =(const float*)d_in[14];
  const float* cW  =(const float*)d_in[15];
  const float* cb  =(const float*)d_in[16];
  float* out=(float*)d_out;

  cudaFuncSetAttribute(k_enc, cudaFuncAttributeMaxDynamicSharedMemorySize, 99328);
  cudaFuncSetAttribute(k_dec, cudaFuncAttributeMaxDynamicSharedMemorySize, 164864);

  k_prep<<<25600,256>>>();
  k_tr_all<<<20096,dim3(32,8)>>>(eWhf, eWhb, dWi, dWh, gW);
  k_xpre<<<dim3(200,32,2),256>>>(orig, emb, eWif, ebf, eWib, ebb);
  k_enc<<<128,256,99328>>>();
  k_dinit<<<64,256>>>();
  k_dec<<<148,256,164864>>>(emb, db, gb, sAw, cAw, out);
  k_cls<<<dim3(32,5),256>>>(cW, cb, out);
}

// round 9
// speedup vs baseline: 1.1862x; 1.1153x over previous
#include <cuda_runtime.h>
#include <math.h>

#define TT2 400
#define HH 512
#define VV 32000

__device__ float g_Xpre[2][12800u*2048];
__device__ float g_WT[4][HH*2048];      // [k][j] : encf,encb,decWih,decWhh
__device__ float g_attT[2][HH*HH];      // [k][col]
__device__ float g_genT[HH*VV];         // [k][v]
__device__ float g_h[2][2][32*HH];
__device__ float g_mem[12800u*HH];      // fwd writes, then combined
__device__ float g_memB[12800u*HH];     // bwd writes
__device__ float g_dh[2][32*HH];
__device__ int   g_w[32];
__device__ float g_lse[32];
__device__ float g_D[64*HH];
__device__ float g_Sc[12800u*64];
__device__ float g_Z[2048];
__device__ float g_V[64*HH];
__device__ float g_vts[64*32*HH];
__device__ float g_logits[32u*VV];
__device__ unsigned g_bc[4];

__device__ __forceinline__ float sigf(float x){ return 1.f/(1.f+expf(-x)); }

__device__ __forceinline__ void gbar(int w, unsigned nblk){
  __syncthreads();
  if (threadIdx.x==0){
    __threadfence();
    unsigned my = atomicAdd(&g_bc[w],1u);
    unsigned tgt = (my/nblk+1u)*nblk;
    while (*(volatile unsigned*)&g_bc[w] < tgt) {}
  }
  __syncthreads();
}

__global__ void k_prep(){
  int i=blockIdx.x*256+threadIdx.x;
  if(i<65536) ((float*)g_h)[i]=0.f;
}

__global__ void k_tr_all(const float* __restrict__ eWhf, const float* __restrict__ eWhb,
                         const float* __restrict__ dWi, const float* __restrict__ dWh,
                         const float* __restrict__ sAw, const float* __restrict__ cAw,
                         const float* __restrict__ gW){
  __shared__ float t[32][33];
  int blk=blockIdx.x;
  const float* W; float* Wt; int R,C,tIdx;
  if(blk<4096){
    int mat=blk>>10; tIdx=blk&1023; R=2048; C=512;
    W = mat==0?eWhf: mat==1?eWhb: mat==2?dWi:dWh;
    Wt = g_WT[mat];
  } else if(blk<4608){
    int mat=(blk-4096)>>8; tIdx=(blk-4096)&255; R=512; C=512;
    W = mat? cAw : sAw; Wt = g_attT[mat];
  } else {
    tIdx=blk-4608; R=VV; C=512; W=gW; Wt=g_genT;
  }
  int r0=(tIdx>>4)*32, c0=(tIdx&15)*32;
  int x=threadIdx.x, y=threadIdx.y;
  #pragma unroll
  for(int i=0;i<32;i+=8) t[y+i][x]=W[(size_t)(r0+y+i)*C+c0+x];
  __syncthreads();
  #pragma unroll
  for(int i=0;i<32;i+=8) Wt[(size_t)(c0+y+i)*R+r0+x]=t[x][y+i];
}

__global__ void k_xpre(const int* __restrict__ orig, const float* __restrict__ emb,
                       const float* __restrict__ Wf, const float* __restrict__ bf,
                       const float* __restrict__ Wb, const float* __restrict__ bb){
  __shared__ float As[16][68], Bs[16][68];
  __shared__ int tokS[64];
  int dir=blockIdx.z;
  const float* W   = dir?Wb:Wf;
  const float* bias= dir?bb:bf;
  int m0=blockIdx.x*64, n0=blockIdx.y*64, tid=threadIdx.x;
  if(tid<64){ int m=m0+tid; tokS[tid]=orig[(m&31)*TT2+(m>>5)]; }
  __syncthreads();
  float acc[4][4];
  #pragma unroll
  for(int i=0;i<4;i++)
    #pragma unroll
    for(int j=0;j<4;j++) acc[i][j]=0.f;
  int tx=tid&15, ty=tid>>4, lm=tid>>2, lk=(tid&3)*4;
  for(int kb=0;kb<HH;kb+=16){
    float4 a=*(const float4*)(emb+(size_t)tokS[lm]*HH+kb+lk);
    As[lk][lm]=a.x; As[lk+1][lm]=a.y; As[lk+2][lm]=a.z; As[lk+3][lm]=a.w;
    float4 bv=*(const float4*)(W+(size_t)(n0+lm)*HH+kb+lk);
    Bs[lk][lm]=bv.x; Bs[lk+1][lm]=bv.y; Bs[lk+2][lm]=bv.z; Bs[lk+3][lm]=bv.w;
    __syncthreads();
    #pragma unroll
    for(int k=0;k<16;k++){
      float4 af=*(const float4*)&As[k][ty*4];
      float4 bf4=*(const float4*)&Bs[k][tx*4];
      float av[4]={af.x,af.y,af.z,af.w}, bv2[4]={bf4.x,bf4.y,bf4.z,bf4.w};
      #pragma unroll
      for(int i=0;i<4;i++)
        #pragma unroll
        for(int j=0;j<4;j++) acc[i][j]+=av[i]*bv2[j];
    }
    __syncthreads();
  }
  float* o=g_Xpre[dir];
  float4 bias4=*(const float4*)(bias+n0+tx*4);
  #pragma unroll
  for(int i=0;i<4;i++){
    int m=m0+ty*4+i;
    float4 r; r.x=acc[i][0]+bias4.x; r.y=acc[i][1]+bias4.y;
    r.z=acc[i][2]+bias4.z; r.w=acc[i][3]+bias4.w;
    *(float4*)(o+(size_t)m*2048+n0+tx*4)=r;
  }
}

// encoder: 128 blocks x 512 thr. block: dir=blk>>6, 8 cols. ksplit 16.
__global__ void __launch_bounds__(512,1) k_enc(){
  extern __shared__ float sm[];
  float* sh=sm;           // 16384
  float* red=sm+16384;    // 512*33
  __shared__ float xg[4][8][32];
  __shared__ float rsum[1024];
  int blk=blockIdx.x, dir=blk>>6, tid=threadIdx.x;
  int cb=(blk&63)*8;
  int q=tid>>5, r=tid&31, gate=r>>3, col=cb+(r&7);
  int j=gate*HH+col, k0=q*32;
  const float* Wt=g_WT[dir];
  int cl=tid>>5, b2=tid&31, c=cb+cl;
  float cc=0.f;
  int bw=2+dir;
  for(int t=0;t<TT2;t++){
    int par=t&1, tt=dir?(TT2-1-t):t;
    const float* xbase = g_Xpre[dir] + (size_t)tt*32*2048;
    #pragma unroll
    for(int p=0;p<2;p++){
      int idx=p*512+tid;
      int g=idx>>8, rem=idx&255, b=rem>>3, ccx=rem&7;
      xg[g][ccx][b]=xbase[(size_t)b*2048+g*512+cb+ccx];
    }
    const float4* h4=(const float4*)g_h[dir][par];
    float4* s4=(float4*)sh;
    #pragma unroll
    for(int i=0;i<8;i++) s4[tid+i*512]=__ldcg(h4+tid+i*512);
    __syncthreads();
    float acc[32];
    #pragma unroll
    for(int b=0;b<32;b++) acc[b]=0.f;
    #pragma unroll 2
    for(int kk=0;kk<8;kk++){
      float w0=Wt[(size_t)(k0+kk*4+0)*2048+j];
      float w1=Wt[(size_t)(k0+kk*4+1)*2048+j];
      float w2=Wt[(size_t)(k0+kk*4+2)*2048+j];
      float w3=Wt[(size_t)(k0+kk*4+3)*2048+j];
      const float* hb=sh+k0+kk*4;
      #pragma unroll
      for(int b=0;b<32;b++){
        float4 h=*(const float4*)(hb+b*HH);
        acc[b]+=w0*h.x+w1*h.y+w2*h.z+w3*h.w;
      }
    }
    #pragma unroll
    for(int b=0;b<32;b++) red[(q*32+r)*33+b]=acc[b];
    __syncthreads();
    #pragma unroll
    for(int u=0;u<2;u++){
      int o=tid*2+u, rr=o>>5, bo=o&31;
      float s=0.f;
      #pragma unroll
      for(int qq=0;qq<16;qq++) s+=red[(qq*32+rr)*33+bo];
      rsum[o]=s;
    }
    __syncthreads();
    if(tid<256){
      float i_=sigf(rsum[(0*8+cl)*32+b2]+xg[0][cl][b2]);
      float f_=sigf(rsum[(1*8+cl)*32+b2]+xg[1][cl][b2]);
      float gg=tanhf(rsum[(2*8+cl)*32+b2]+xg[2][cl][b2]);
      float o_=sigf(rsum[(3*8+cl)*32+b2]+xg[3][cl][b2]);
      cc=f_*cc+i_*gg;
      float hn=o_*tanhf(cc);
      g_h[dir][1-par][b2*HH+c]=hn;
      if(dir==0) g_mem [((size_t)tt*32+b2)*HH+c]=hn;
      else       g_memB[((size_t)tt*32+b2)*HH+c]=hn;
    }
    gbar(bw,64);
  }
}

__global__ void k_dinit(){
  size_t i=(size_t)blockIdx.x*256+threadIdx.x;
  if(i<12800u*HH) g_mem[i]+=g_memB[i];
  if(i<16384) g_dh[0][i]=g_h[0][0][i]+g_h[1][0][i];
  if(i<32) g_w[i]=1;
}

// decoder: 148 blocks x 512 thr
__global__ void __launch_bounds__(512,1) k_dec(const float* __restrict__ emb,
    const float* __restrict__ db, const float* __restrict__ genb,
    float* __restrict__ out){
  extern __shared__ float sm[];
  float* sh=sm;            // 32768: [0..16383] h, [16384..32767] x
  float* red=sm+32768;     // 512*33
  __shared__ __align__(16) float sbuf[6400];  // A 2176 | B 2176 | sZ 2048
  __shared__ int tok[32];
  float* A=sbuf; float* B=sbuf+2176; float* sZ=sbuf+4352;
  int blk=blockIdx.x, tid=threadIdx.x;
  float cc=0.f;
  for(int s=0;s<64;s++){
    int par=s&1;
    // ---- P1: cell (blocks 0..127) ; wb half 1 (128..147)
    if(blk<128){
      if(tid<32) tok[tid]=__ldcg(&g_w[tid]);
      const float4* h4=(const float4*)g_dh[par];
      float4* s4=(float4*)sh;
      #pragma unroll
      for(int i=0;i<8;i++) s4[tid+i*512]=__ldcg(h4+tid+i*512);
      __syncthreads();
      float4* x4=s4+4096;
      const float4* e4=(const float4*)emb;
      #pragma unroll
      for(int i=0;i<8;i++){ int ii=tid+i*512; x4[ii]=e4[(size_t)tok[ii>>7]*128+(ii&127)]; }
      __syncthreads();
      int q=tid>>4, r=tid&15, gate=r>>2, cb=blk*4, col=cb+(r&3);
      int j=gate*HH+col, k0=q*16;
      float acc[32];
      #pragma unroll
      for(int b=0;b<32;b++) acc[b]=0.f;
      #pragma unroll
      for(int kk=0;kk<4;kk++){
        float wh[4],wi[4];
        #pragma unroll
        for(int i2=0;i2<4;i2++){ wh[i2]=g_WT[3][(size_t)(k0+kk*4+i2)*2048+j];
                                 wi[i2]=g_WT[2][(size_t)(k0+kk*4+i2)*2048+j]; }
        const float* hb=sh+k0+kk*4; const float* xb=sh+16384+k0+kk*4;
        #pragma unroll
        for(int b=0;b<32;b++){
          float4 h=*(const float4*)(hb+b*HH); float4 x=*(const float4*)(xb+b*HH);
          acc[b]+=wh[0]*h.x+wh[1]*h.y+wh[2]*h.z+wh[3]*h.w
                 +wi[0]*x.x+wi[1]*x.y+wi[2]*x.z+wi[3]*x.w;
        }
      }
      #pragma unroll
      for(int b=0;b<32;b++) red[(q*16+r)*33+b]=acc[b];
      __syncthreads();
      { int o=tid, rr=o>>5, bo=o&31;
        float s2=0.f;
        #pragma unroll
        for(int qq=0;qq<32;qq++) s2+=red[(qq*16+rr)*33+bo];
        sZ[o]=s2; }   // rsum alias
      __syncthreads();
      if(tid<128){
        int cl=tid>>5, b2=tid&31, c=blk*4+cl;
        float i_=sigf(sZ[(0*4+cl)*32+b2]+db[c]);
        float f_=sigf(sZ[(1*4+cl)*32+b2]+db[HH+c]);
        float gg=tanhf(sZ[(2*4+cl)*32+b2]+db[2*HH+c]);
        float o_=sigf(sZ[(3*4+cl)*32+b2]+db[3*HH+c]);
        cc=f_*cc+i_*gg;
        g_dh[1-par][b2*HH+c]=o_*tanhf(cc);
      }
    } else if(s>0){
      for(unsigned idx=(blk-128)*512+tid; idx<512000u; idx+=20u*512){
        unsigned b=idx/32000u, v=idx-b*32000u;
        out[((size_t)b*64+(s-1))*VV+v]=__ldcg(&g_logits[(size_t)b*VV+v])-__ldcg(&g_lse[b]);
      }
    }
    gbar(1,148);
    // ---- P2: D (0..63) ; zero Z,V + wb half 2 (64..147)
    if(blk<64){
      int mat=blk>>5, cb2=(blk&31)*16;
      const float4* h4=(const float4*)g_dh[1-par];
      float4* s4=(float4*)sh;
      #pragma unroll
      for(int i=0;i<8;i++) s4[tid+i*512]=__ldcg(h4+tid+i*512);
      __syncthreads();
      int q=tid>>4, r=tid&15, col=cb2+r, k0=q*16;
      const float* At=g_attT[mat];
      float acc[32];
      #pragma unroll
      for(int b=0;b<32;b++) acc[b]=0.f;
      #pragma unroll
      for(int kk=0;kk<4;kk++){
        float w0=At[(size_t)(k0+kk*4+0)*HH+col];
        float w1=At[(size_t)(k0+kk*4+1)*HH+col];
        float w2=At[(size_t)(k0+kk*4+2)*HH+col];
        float w3=At[(size_t)(k0+kk*4+3)*HH+col];
        const float* hb=sh+k0+kk*4;
        #pragma unroll
        for(int b=0;b<32;b++){
          float4 h=*(const float4*)(hb+b*HH);
          acc[b]+=w0*h.x+w1*h.y+w2*h.z+w3*h.w;
        }
      }
      #pragma unroll
      for(int b=0;b<32;b++) red[(q*16+r)*33+b]=acc[b];
      __syncthreads();
      { int o=tid, rr=o>>5, bo=o&31;
        float s2=0.f;
        #pragma unroll
        for(int qq=0;qq<32;qq++) s2+=red[(qq*16+rr)*33+bo];
        g_D[(size_t)(mat*32+bo)*HH+cb2+rr]=s2; }
    } else {
      int base=(blk-64)*512+tid;
      if(base<2048) g_Z[base]=0.f;
      if(base<32768) g_V[base]=0.f;
      if(s>0){
        for(unsigned idx=512000u+base; idx<1024000u; idx+=84u*512){
          unsigned b=idx/32000u, v=idx-b*32000u;
          out[((size_t)b*64+(s-1))*VV+v]=__ldcg(&g_logits[(size_t)b*VV+v])-__ldcg(&g_lse[b]);
        }
      }
    }
    gbar(1,148);
    // ---- P3: Sc = exp(tanh(mem @ D^T)) + Z  (400 jobs of 32 rows)
    {
      for(int i=tid;i<2048;i+=512) sZ[i]=0.f;
      __syncthreads();
      int tx=tid&15, ty=tid>>4;
      int lmA=tid>>4, lkA=(tid&15)*2;
      int lmB=tid>>3, lkB=(tid&7)*4;
      for(int job=blk;job<400;job+=148){
        int m0=job*32;
        float4 acc={0.f,0.f,0.f,0.f};
        for(int kb=0;kb<HH;kb+=32){
          float2 a=*(const float2*)(g_mem+(size_t)(m0+lmA)*HH+kb+lkA);
          A[lkA*68+lmA]=a.x; A[(lkA+1)*68+lmA]=a.y;
          float4 bv=__ldcg((const float4*)(g_D+(size_t)lmB*HH+kb+lkB));
          B[lkB*68+lmB]=bv.x; B[(lkB+1)*68+lmB]=bv.y;
          B[(lkB+2)*68+lmB]=bv.z; B[(lkB+3)*68+lmB]=bv.w;
          __syncthreads();
          #pragma unroll 8
          for(int k=0;k<32;k++){
            float a1=A[k*68+ty];
            float4 b4=*(const float4*)&B[k*68+tx*4];
            acc.x+=a1*b4.x; acc.y+=a1*b4.y; acc.z+=a1*b4.z; acc.w+=a1*b4.w;
          }
          __syncthreads();
        }
        int m=m0+ty, zr=m&31;
        float4 e;
        e.x=expf(tanhf(acc.x)); e.y=expf(tanhf(acc.y));
        e.z=expf(tanhf(acc.z)); e.w=expf(tanhf(acc.w));
        *(float4*)(g_Sc+(size_t)m*64+tx*4)=e;
        atomicAdd(&sZ[(tx*4+0)*32+zr],e.x);
        atomicAdd(&sZ[(tx*4+1)*32+zr],e.y);
        atomicAdd(&sZ[(tx*4+2)*32+zr],e.z);
        atomicAdd(&sZ[(tx*4+3)*32+zr],e.w);
      }
      __syncthreads();
      for(int i=tid;i<2048;i+=512) atomicAdd(&g_Z[i],sZ[i]);
    }
    gbar(1,148);
    // ---- P4: V = beta^T @ mem  (400 jobs: 8 h-tiles x 50 row-chunks of 256)
    {
      for(int i=tid;i<2048;i+=512) sZ[i]=1.f/__ldcg(&g_Z[i]);
      __syncthreads();
      int tx=tid&15, ty4=tid>>4;
      int lk=tid>>4, lc=(tid&15)*4;
      for(int job=blk;job<400;job+=148){
        int h0=(job&7)*64;
        size_t r0=(size_t)(job>>3)*256;
        float4 acc0={0.f,0.f,0.f,0.f}, acc1={0.f,0.f,0.f,0.f};
        for(int ch=0;ch<8;ch++){
          size_t rb=r0+ch*32;
          float4 sc=__ldcg((const float4*)(g_Sc+(rb+lk)*64+lc));
          int zr=(int)((rb+lk)&31);
          A[lk*68+lc+0]=sc.x*sZ[(lc+0)*32+zr];
          A[lk*68+lc+1]=sc.y*sZ[(lc+1)*32+zr];
          A[lk*68+lc+2]=sc.z*sZ[(lc+2)*32+zr];
          A[lk*68+lc+3]=sc.w*sZ[(lc+3)*32+zr];
          float4 mv=*(const float4*)(g_mem+(rb+lk)*HH+h0+lc);
          B[lk*68+lc+0]=mv.x; B[lk*68+lc+1]=mv.y;
          B[lk*68+lc+2]=mv.z; B[lk*68+lc+3]=mv.w;
          __syncthreads();
          #pragma unroll 8
          for(int k=0;k<32;k++){
            float a0=A[k*68+ty4], a1=A[k*68+ty4+32];
            float4 b4=*(const float4*)&B[k*68+tx*4];
            acc0.x+=a0*b4.x; acc0.y+=a0*b4.y; acc0.z+=a0*b4.z; acc0.w+=a0*b4.w;
            acc1.x+=a1*b4.x; acc1.y+=a1*b4.y; acc1.z+=a1*b4.z; acc1.w+=a1*b4.w;
          }
          __syncthreads();
        }
        atomicAdd(&g_V[(size_t)ty4*HH+h0+tx*4+0],acc0.x);
        atomicAdd(&g_V[(size_t)ty4*HH+h0+tx*4+1],acc0.y);
        atomicAdd(&g_V[(size_t)ty4*HH+h0+tx*4+2],acc0.z);
        atomicAdd(&g_V[(size_t)ty4*HH+h0+tx*4+3],acc0.w);
        atomicAdd(&g_V[(size_t)(ty4+32)*HH+h0+tx*4+0],acc1.x);
        atomicAdd(&g_V[(size_t)(ty4+32)*HH+h0+tx*4+1],acc1.y);
        atomicAdd(&g_V[(size_t)(ty4+32)*HH+h0+tx*4+2],acc1.z);
        atomicAdd(&g_V[(size_t)(ty4+32)*HH+h0+tx*4+3],acc1.w);
      }
    }
    gbar(1,148);
    // ---- P5: logits (0..124), vts (125)
    if(blk<125){
      float4* s4=(float4*)sh;
      const float4* v4=(const float4*)g_V;
      #pragma unroll
      for(int i=0;i<8;i++) s4[tid+i*512]=__ldcg(v4+tid+i*512);
      __syncthreads();
      int v=blk*256+(tid>>1);
      int khalf=(tid&1)*256;
      float acc[32];
      #pragma unroll
      for(int b=0;b<32;b++) acc[b]=0.f;
      for(int k2=0;k2<64;k2++){
        int k=khalf+k2*4;
        float w0=__ldcg(&g_genT[(size_t)(k+0)*VV+v]);
        float w1=__ldcg(&g_genT[(size_t)(k+1)*VV+v]);
        float w2=__ldcg(&g_genT[(size_t)(k+2)*VV+v]);
        float w3=__ldcg(&g_genT[(size_t)(k+3)*VV+v]);
        #pragma unroll
        for(int b=0;b<32;b++){
          float4 x=*(const float4*)(sh+b*HH+k);
          acc[b]+=w0*x.x+w1*x.y+w2*x.z+w3*x.w;
        }
      }
      #pragma unroll
      for(int b=0;b<32;b++) acc[b]+=__shfl_xor_sync(0xffffffffu,acc[b],1);
      if(!(tid&1)){
        float bb2=genb[v];
        #pragma unroll
        for(int b=0;b<32;b++) g_logits[(size_t)b*VV+v]=acc[b]+bb2;
      }
      __syncthreads();
    } else if(blk==125){
      for(int i=tid;i<16384;i+=512) g_vts[(size_t)s*16384+i]=__ldcg(&g_V[16384+i]);
    }
    gbar(1,148);
    // ---- P6: lse + argmax (0..31)
    if(blk<32){
      float* mx=sbuf; float* ss=sbuf+512; int* ii=(int*)(sbuf+1024);
      const float* lg=g_logits+(size_t)blk*VV;
      float m=-1e30f,sum=0.f; int idx=0;
      for(int v=tid;v<VV;v+=512){
        float l=__ldcg(&lg[v]);
        if(l>m){ sum=sum*expf(m-l)+1.f; m=l; idx=v; }
        else sum+=expf(l-m);
      }
      mx[tid]=m; ss[tid]=sum; ii[tid]=idx;
      __syncthreads();
      for(int o=256;o;o>>=1){
        if(tid<o){
          float m1=mx[tid],m2=mx[tid+o],s1=ss[tid],s2=ss[tid+o];
          int i1=ii[tid],i2=ii[tid+o];
          float M=fmaxf(m1,m2);
          ss[tid]=s1*expf(m1-M)+s2*expf(m2-M);
          mx[tid]=M;
          ii[tid]=(m2>m1)?i2:(m1>m2?i1:min(i1,i2));
        }
        __syncthreads();
      }
      if(tid==0){ g_lse[blk]=mx[0]+logf(ss[0]); g_w[blk]=ii[0]; }
    }
    gbar(1,148);
  }
  // tail: writeback s=63
  for(unsigned idx=blk*512+tid; idx<1024000u; idx+=148u*512){
    unsigned b=idx/32000u, v=idx-b*32000u;
    out[((size_t)b*64+63)*VV+v]=__ldcg(&g_logits[(size_t)b*VV+v])-__ldcg(&g_lse[b]);
  }
}

__global__ void k_cls(const float* __restrict__ W, const float* __restrict__ cb,
                      float* __restrict__ out){
  __shared__ float rr[256];
  int b=blockIdx.x, l=blockIdx.y, tid=threadIdx.x;
  const float* wr=W+(size_t)l*237568;
  float acc=0.f;
  for(int k=tid;k<32768;k+=256)
    acc+=wr[k]*g_vts[(size_t)(k>>9)*16384+b*HH+(k&511)];
  for(int k=32768+tid;k<237568;k+=256){
    int kk=k-32768;
    acc+=wr[k]*g_mem[((size_t)(kk>>9)*32+b)*HH+(kk&511)];
  }
  rr[tid]=acc;
  __syncthreads();
  for(int o=128;o;o>>=1){ if(tid<o) rr[tid]+=rr[tid+o]; __syncthreads(); }
  if(tid==0) out[65536000u+b*5+l]=rr[0]+cb[l];
}

extern "C" void kernel_launch(void* const* d_in, const int* in_sizes, int n_in,
                              void* d_out, int out_size){
  const int*   orig=(const int*)  d_in[0];
  const float* emb =(const float*)d_in[1];
  const float* eWif=(const float*)d_in[2];
  const float* eWhf=(const float*)d_in[3];
  const float* ebf =(const float*)d_in[4];
  const float* eWib=(const float*)d_in[5];
  const float* eWhb=(const float*)d_in[6];
  const float* ebb =(const float*)d_in[7];
  const float* dWi =(const float*)d_in[8];
  const float* dWh =(const float*)d_in[9];
  const float* db  =(const float*)d_in[10];
  const float* sAw =(const float*)d_in[11];
  const float* cAw =(const float*)d_in[12];
  const float* gW  =(const float*)d_in[13];
  const float* gb  =(const float*)d_in[14];
  const float* cW  =(const float*)d_in[15];
  const float* cb  =(const float*)d_in[16];
  float* out=(float*)d_out;

  cudaFuncSetAttribute(k_enc, cudaFuncAttributeMaxDynamicSharedMemorySize, 133120);
  cudaFuncSetAttribute(k_dec, cudaFuncAttributeMaxDynamicSharedMemorySize, 198656);

  k_prep<<<256,256>>>();
  k_tr_all<<<20608,dim3(32,8)>>>(eWhf, eWhb, dWi, dWh, sAw, cAw, gW);
  k_xpre<<<dim3(200,32,2),256>>>(orig, emb, eWif, ebf, eWib, ebb);
  k_enc<<<128,512,133120>>>();
  k_dinit<<<25600,256>>>();
  k_dec<<<148,512,198656>>>(emb, db, gb, out);
  k_cls<<<dim3(32,5),256>>>(cW, cb, out);
}

// round 11
// speedup vs baseline: 1.3421x; 1.1314x over previous
#include <cuda_runtime.h>
#include <math.h>

#define TT2 400
#define HH 512
#define VV 32000
#define NB 296   // decoder blocks
#define J3 200
#define J4 256
#define J5 250

__device__ float g_Xpre[2][12800u*2048];
__device__ float g_WT[4][HH*2048];      // [k][j]: encf,encb,decWih,decWhh
__device__ float g_attT[2][HH*HH];      // [k][col]
__device__ float g_genT[HH*VV];         // [k][v]
__device__ float g_h[2][2][32*HH];
__device__ float g_mem[12800u*HH];
__device__ float g_memB[12800u*HH];
__device__ float g_dh[2][32*HH];
__device__ int   g_w[32];
__device__ float g_lse[32];
__device__ float g_D[64*HH];
__device__ float g_Sc[12800u*64];
__device__ float g_Z[2048];
__device__ float g_V[64*HH];
__device__ float g_vts[64*32*HH];
__device__ float g_logits[32u*VV];
__device__ unsigned g_bc[4];
__device__ unsigned g_q[3];

__device__ __forceinline__ float sigf(float x){ return 1.f/(1.f+expf(-x)); }

__device__ __forceinline__ void gbar(int w, unsigned nblk){
  __syncthreads();
  if (threadIdx.x==0){
    __threadfence();
    unsigned my = atomicAdd(&g_bc[w],1u);
    unsigned tgt = (my/nblk+1u)*nblk;
    while (*(volatile unsigned*)&g_bc[w] < tgt) {}
  }
  __syncthreads();
}

__global__ void k_prep(){
  int i=blockIdx.x*256+threadIdx.x;
  if(i<65536) ((float*)g_h)[i]=0.f;
  if(i<4) g_bc[i]=0u;
  if(i<3) g_q[i]=0u;
}

__global__ void k_tr_all(const float* __restrict__ eWhf, const float* __restrict__ eWhb,
                         const float* __restrict__ dWi, const float* __restrict__ dWh,
                         const float* __restrict__ sAw, const float* __restrict__ cAw,
                         const float* __restrict__ gW){
  __shared__ float t[32][33];
  int blk=blockIdx.x;
  const float* W; float* Wt; int R,C,tIdx;
  if(blk<4096){
    int mat=blk>>10; tIdx=blk&1023; R=2048; C=512;
    W = mat==0?eWhf: mat==1?eWhb: mat==2?dWi:dWh;
    Wt = g_WT[mat];
  } else if(blk<4608){
    int mat=(blk-4096)>>8; tIdx=(blk-4096)&255; R=512; C=512;
    W = mat? cAw : sAw; Wt = g_attT[mat];
  } else {
    tIdx=blk-4608; R=VV; C=512; W=gW; Wt=g_genT;
  }
  int r0=(tIdx>>4)*32, c0=(tIdx&15)*32;
  int x=threadIdx.x, y=threadIdx.y;
  #pragma unroll
  for(int i=0;i<32;i+=8) t[y+i][x]=W[(size_t)(r0+y+i)*C+c0+x];
  __syncthreads();
  #pragma unroll
  for(int i=0;i<32;i+=8) Wt[(size_t)(c0+y+i)*R+r0+x]=t[x][y+i];
}

// Xpre: 128x64 tile, 8x4 micro
__global__ void k_xpre(const int* __restrict__ orig, const float* __restrict__ emb,
                       const float* __restrict__ Wf, const float* __restrict__ bf,
                       const float* __restrict__ Wb, const float* __restrict__ bb){
  __shared__ float As[16][132], Bs[16][68];
  __shared__ int tokS[128];
  int dir=blockIdx.z;
  const float* W   = dir?Wb:Wf;
  const float* bias= dir?bb:bf;
  int m0=blockIdx.x*128, n0=blockIdx.y*64, tid=threadIdx.x;
  if(tid<128){ int m=m0+tid; tokS[tid]=orig[(m&31)*TT2+(m>>5)]; }
  __syncthreads();
  float acc[8][4];
  #pragma unroll
  for(int i=0;i<8;i++)
    #pragma unroll
    for(int j=0;j<4;j++) acc[i][j]=0.f;
  int tx=tid&15, ty=tid>>4;
  int lm2=tid>>2, lk=(tid&3)*4;
  for(int kb=0;kb<HH;kb+=16){
    #pragma unroll
    for(int p=0;p<2;p++){
      int idx=p*256+tid, lm=idx>>2, lkk=(idx&3)*4;
      float4 a=*(const float4*)(emb+(size_t)tokS[lm]*HH+kb+lkk);
      As[lkk][lm]=a.x; As[lkk+1][lm]=a.y; As[lkk+2][lm]=a.z; As[lkk+3][lm]=a.w;
    }
    float4 bv=*(const float4*)(W+(size_t)(n0+lm2)*HH+kb+lk);
    Bs[lk][lm2]=bv.x; Bs[lk+1][lm2]=bv.y; Bs[lk+2][lm2]=bv.z; Bs[lk+3][lm2]=bv.w;
    __syncthreads();
    #pragma unroll
    for(int k=0;k<16;k++){
      float4 a0=*(const float4*)&As[k][ty*8];
      float4 a1=*(const float4*)&As[k][ty*8+4];
      float4 b4=*(const float4*)&Bs[k][tx*4];
      float av[8]={a0.x,a0.y,a0.z,a0.w,a1.x,a1.y,a1.z,a1.w};
      float bvv[4]={b4.x,b4.y,b4.z,b4.w};
      #pragma unroll
      for(int i=0;i<8;i++)
        #pragma unroll
        for(int j=0;j<4;j++) acc[i][j]+=av[i]*bvv[j];
    }
    __syncthreads();
  }
  float* o=g_Xpre[dir];
  float4 bias4=*(const float4*)(bias+n0+tx*4);
  #pragma unroll
  for(int i=0;i<8;i++){
    int m=m0+ty*8+i;
    float4 r; r.x=acc[i][0]+bias4.x; r.y=acc[i][1]+bias4.y;
    r.z=acc[i][2]+bias4.z; r.w=acc[i][3]+bias4.w;
    *(float4*)(o+(size_t)m*2048+n0+tx*4)=r;
  }
}

// encoder: 256 blocks x 256 thr (2/SM). dir=blk>>7, 4 cols per block.
__global__ void __launch_bounds__(256,2) k_enc(){
  extern __shared__ float sm[];
  float* sh=sm;               // 16384
  float* red=sm+16384;        // 8448
  float* rsum=red+8448;       // 512
  float* xg=rsum+512;         // 512 : [g][cl][b] = ((g*4+cl)*32+b)
  int blk=blockIdx.x, dir=blk>>7, tid=threadIdx.x;
  int ct=(blk&127)*4;
  int q=tid>>4, r=tid&15, gate=r>>2, cl0=r&3;
  int j=gate*HH+ct+cl0, k0=q*32;
  const float* Wt=g_WT[dir];
  float cc=0.f;
  int bw=2+dir;
  for(int t=0;t<TT2;t++){
    int par=t&1, tt=dir?(TT2-1-t):t;
    const float* xbase = g_Xpre[dir] + (size_t)tt*32*2048;
    #pragma unroll
    for(int p=0;p<2;p++){
      int idx=p*256+tid;
      int g=idx>>7, rem=idx&127, b=rem>>2, c2=rem&3;
      xg[(g*4+c2)*32+b]=xbase[(size_t)b*2048+g*512+ct+c2];
    }
    const float4* h4=(const float4*)g_h[dir][par];
    float4* s4=(float4*)sh;
    #pragma unroll
    for(int i=0;i<16;i++) s4[tid+i*256]=__ldcg(h4+tid+i*256);
    __syncthreads();
    float acc[32];
    #pragma unroll
    for(int b=0;b<32;b++) acc[b]=0.f;
    #pragma unroll 2
    for(int kk=0;kk<8;kk++){
      float w0=Wt[(size_t)(k0+kk*4+0)*2048+j];
      float w1=Wt[(size_t)(k0+kk*4+1)*2048+j];
      float w2=Wt[(size_t)(k0+kk*4+2)*2048+j];
      float w3=Wt[(size_t)(k0+kk*4+3)*2048+j];
      const float* hb=sh+k0+kk*4;
      #pragma unroll
      for(int b=0;b<32;b++){
        float4 h=*(const float4*)(hb+b*HH);
        acc[b]+=w0*h.x+w1*h.y+w2*h.z+w3*h.w;
      }
    }
    #pragma unroll
    for(int b=0;b<32;b++) red[(q*16+r)*33+b]=acc[b];
    __syncthreads();
    #pragma unroll
    for(int u=0;u<2;u++){
      int o=tid*2+u, jl=o>>5, bl=o&31;
      float s=0.f;
      #pragma unroll
      for(int q2=0;q2<16;q2++) s+=red[(q2*16+jl)*33+bl];
      rsum[jl*32+bl]=s;
    }
    __syncthreads();
    if(tid<128){
      int cl=tid>>5, bl=tid&31, c=ct+cl;
      float i_=sigf(rsum[(0*4+cl)*32+bl]+xg[(0*4+cl)*32+bl]);
      float f_=sigf(rsum[(1*4+cl)*32+bl]+xg[(1*4+cl)*32+bl]);
      float gg=tanhf(rsum[(2*4+cl)*32+bl]+xg[(2*4+cl)*32+bl]);
      float o_=sigf(rsum[(3*4+cl)*32+bl]+xg[(3*4+cl)*32+bl]);
      cc=f_*cc+i_*gg;
      float hn=o_*tanhf(cc);
      g_h[dir][1-par][bl*HH+c]=hn;
      if(dir==0) g_mem [((size_t)tt*32+bl)*HH+c]=hn;
      else       g_memB[((size_t)tt*32+bl)*HH+c]=hn;
    }
    gbar(bw,128);
  }
}

__global__ void k_dinit(){
  size_t i=(size_t)blockIdx.x*256+threadIdx.x;
  if(i<12800u*HH) g_mem[i]+=g_memB[i];
  if(i<16384) g_dh[0][i]=g_h[0][0][i]+g_h[1][0][i];
  if(i<32) g_w[i]=1;
}

// decoder: 296 blocks x 256 thr (2/SM)
__global__ void __launch_bounds__(256,2) k_dec(const float* __restrict__ emb,
    const float* __restrict__ db, const float* __restrict__ genb,
    float* __restrict__ out){
  extern __shared__ float sm[];
  float* sh=sm;          // 16384 floats
  float* red=sm+16384;   // 8448 floats
  __shared__ int tok[32];
  __shared__ int sjob;
  int blk=blockIdx.x, tid=threadIdx.x;
  float cc=0.f;
  for(int s=0;s<64;s++){
    int par=s&1;
    // ---- P1: cell (0..255: 128 col-tiles x 2 b-halves) ; wb (256..295)
    if(blk<256){
      int ct=blk>>1, half=blk&1;
      if(tid<32) tok[tid]=__ldcg(&g_w[tid]);
      __syncthreads();
      float4* s4=(float4*)sh;
      const float4* h4=(const float4*)g_dh[par];
      const float4* e4=(const float4*)emb;
      #pragma unroll
      for(int i=0;i<8;i++){
        int idx=i*256+tid;                       // 0..2047
        int bl=idx>>7, k4=idx&127;
        s4[idx]      =__ldcg(h4+(size_t)(half*16+bl)*128+k4);
        s4[2048+idx] =e4[(size_t)tok[half*16+bl]*128+k4];
      }
      __syncthreads();
      int q=tid>>4, r=tid&15, gate=r>>2, cl0=r&3;
      int j=gate*HH+ct*4+cl0, k0=q*32;
      float acc[16];
      #pragma unroll
      for(int b=0;b<16;b++) acc[b]=0.f;
      #pragma unroll 2
      for(int kk=0;kk<8;kk++){
        float wh[4],wi[4];
        #pragma unroll
        for(int i2=0;i2<4;i2++){ wh[i2]=g_WT[3][(size_t)(k0+kk*4+i2)*2048+j];
                                 wi[i2]=g_WT[2][(size_t)(k0+kk*4+i2)*2048+j]; }
        const float* hb=sh+k0+kk*4; const float* xb=sh+8192+k0+kk*4;
        #pragma unroll
        for(int b=0;b<16;b++){
          float4 h=*(const float4*)(hb+b*HH); float4 x=*(const float4*)(xb+b*HH);
          acc[b]+=wh[0]*h.x+wh[1]*h.y+wh[2]*h.z+wh[3]*h.w
                 +wi[0]*x.x+wi[1]*x.y+wi[2]*x.z+wi[3]*x.w;
        }
      }
      #pragma unroll
      for(int b=0;b<16;b++) red[(q*16+r)*17+b]=acc[b];
      __syncthreads();
      { int jl=tid>>4, bl=tid&15;
        float s2=0.f;
        #pragma unroll
        for(int q2=0;q2<16;q2++) s2+=red[(q2*16+jl)*17+bl];
        red[4352+jl*16+bl]=s2; }
      __syncthreads();
      if(tid<64){
        int cl=tid>>4, bl=tid&15;
        int c=ct*4+cl, b=half*16+bl;
        float i_=sigf(red[4352+(0*4+cl)*16+bl]+db[c]);
        float f_=sigf(red[4352+(1*4+cl)*16+bl]+db[HH+c]);
        float gg=tanhf(red[4352+(2*4+cl)*16+bl]+db[2*HH+c]);
        float o_=sigf(red[4352+(3*4+cl)*16+bl]+db[3*HH+c]);
        cc=f_*cc+i_*gg;
        g_dh[1-par][b*HH+c]=o_*tanhf(cc);
      }
    } else if(s>0){
      for(unsigned idx=(blk-256)*256+tid; idx<1024000u; idx+=40u*256){
        unsigned b=idx/32000u, v=idx-b*32000u;
        out[((size_t)b*64+(s-1))*VV+v]=__ldcg(&g_logits[(size_t)b*VV+v])-__ldcg(&g_lse[b]);
      }
    }
    gbar(1,NB);
    // ---- P2: D (0..255, 4 j each) ; zero Z,V (256..295)
    if(blk<256){
      float4* s4=(float4*)sh;
      const float4* h4=(const float4*)g_dh[1-par];
      #pragma unroll
      for(int i=0;i<16;i++) s4[tid+i*256]=__ldcg(h4+tid+i*256);
      __syncthreads();
      int q=tid>>2, r=tid&3;
      int jj=blk*4+r, mat=jj>>9, col=jj&511, k0=q*8;
      const float* At=g_attT[mat];
      float acc[32];
      #pragma unroll
      for(int b=0;b<32;b++) acc[b]=0.f;
      #pragma unroll
      for(int kk=0;kk<2;kk++){
        float w0=At[(size_t)(k0+kk*4+0)*HH+col];
        float w1=At[(size_t)(k0+kk*4+1)*HH+col];
        float w2=At[(size_t)(k0+kk*4+2)*HH+col];
        float w3=At[(size_t)(k0+kk*4+3)*HH+col];
        const float* hb=sh+k0+kk*4;
        #pragma unroll
        for(int b=0;b<32;b++){
          float4 h=*(const float4*)(hb+b*HH);
          acc[b]+=w0*h.x+w1*h.y+w2*h.z+w3*h.w;
        }
      }
      #pragma unroll
      for(int b=0;b<32;b++) red[tid*33+b]=acc[b];
      __syncthreads();
      if(tid<128){
        int jl=tid>>5, bl=tid&31;
        float s2=0.f;
        #pragma unroll
        for(int q2=0;q2<64;q2++) s2+=red[(q2*4+jl)*33+bl];
        int jg=blk*4+jl, mt=jg>>9, cg=jg&511;
        g_D[(size_t)(mt*32+bl)*HH+cg]=s2;
      }
    } else {
      int base=(blk-256)*256+tid;
      for(int i=base;i<2048;i+=40*256) g_Z[i]=0.f;
      for(int i=base;i<32768;i+=40*256) g_V[i]=0.f;
    }
    gbar(1,NB);
    // ---- P3: Sc = exp(tanh(mem @ D^T)) + Z   (queue, 200 jobs of 64 rows)
    {
      float* sZ=red;            // 2048
      float* A=red+2048;        // 16x68
      float* B=red+3136;        // 16x68
      for(int i=tid;i<2048;i+=256) sZ[i]=0.f;
      unsigned base=(unsigned)s*(J3+NB);
      int tx=tid&15, ty=tid>>4, lm=tid>>2, lk=(tid&3)*4;
      for(;;){
        __syncthreads();
        if(tid==0){ unsigned t=atomicAdd(&g_q[0],1u); sjob=(t<base+J3)?(int)(t-base):-1; }
        __syncthreads();
        int job=sjob; if(job<0) break;
        int m0=job*64;
        float acc[4][4];
        #pragma unroll
        for(int i=0;i<4;i++)
          #pragma unroll
          for(int j2=0;j2<4;j2++) acc[i][j2]=0.f;
        for(int kb=0;kb<HH;kb+=16){
          float4 a=*(const float4*)(g_mem+(size_t)(m0+lm)*HH+kb+lk);
          A[(lk+0)*68+lm]=a.x; A[(lk+1)*68+lm]=a.y; A[(lk+2)*68+lm]=a.z; A[(lk+3)*68+lm]=a.w;
          float4 bv=__ldcg((const float4*)(g_D+(size_t)lm*HH+kb+lk));
          B[(lk+0)*68+lm]=bv.x; B[(lk+1)*68+lm]=bv.y; B[(lk+2)*68+lm]=bv.z; B[(lk+3)*68+lm]=bv.w;
          __syncthreads();
          #pragma unroll
          for(int k=0;k<16;k++){
            float4 af=*(const float4*)&A[k*68+ty*4];
            float4 bf4=*(const float4*)&B[k*68+tx*4];
            float av[4]={af.x,af.y,af.z,af.w}, bvv[4]={bf4.x,bf4.y,bf4.z,bf4.w};
            #pragma unroll
            for(int i=0;i<4;i++)
              #pragma unroll
              for(int j2=0;j2<4;j2++) acc[i][j2]+=av[i]*bvv[j2];
          }
          __syncthreads();
        }
        #pragma unroll
        for(int i=0;i<4;i++){
          int m=m0+ty*4+i, zr=m&31;
          float4 e;
          e.x=expf(tanhf(acc[i][0])); e.y=expf(tanhf(acc[i][1]));
          e.z=expf(tanhf(acc[i][2])); e.w=expf(tanhf(acc[i][3]));
          *(float4*)(g_Sc+(size_t)m*64+tx*4)=e;
          atomicAdd(&sZ[(tx*4+0)*32+zr],e.x);
          atomicAdd(&sZ[(tx*4+1)*32+zr],e.y);
          atomicAdd(&sZ[(tx*4+2)*32+zr],e.z);
          atomicAdd(&sZ[(tx*4+3)*32+zr],e.w);
        }
      }
      __syncthreads();
      for(int i=tid;i<2048;i+=256) atomicAdd(&g_Z[i],sZ[i]);
    }
    gbar(1,NB);
    // ---- P4: V = beta^T @ mem   (queue, 256 jobs: 8 h-tiles x 32 k-chunks of 400)
    {
      float* zi=red;            // 2048
      float* A=red+2048;
      float* B=red+3136;
      for(int i=tid;i<2048;i+=256) zi[i]=1.f/__ldcg(&g_Z[i]);
      unsigned base=(unsigned)s*(J4+NB);
      int tx=tid&15, ty=tid>>4;
      int lk2=tid>>4, lc=(tid&15)*4;
      for(;;){
        __syncthreads();
        if(tid==0){ unsigned t=atomicAdd(&g_q[1],1u); sjob=(t<base+J4)?(int)(t-base):-1; }
        __syncthreads();
        int job=sjob; if(job<0) break;
        int h0=(job&7)*64;
        size_t r0=(size_t)(job>>3)*400;
        float acc[4][4];
        #pragma unroll
        for(int i=0;i<4;i++)
          #pragma unroll
          for(int j2=0;j2<4;j2++) acc[i][j2]=0.f;
        for(int ch=0;ch<25;ch++){
          size_t rb=r0+ch*16;
          float4 sc=__ldcg((const float4*)(g_Sc+(rb+lk2)*64+lc));
          int zr=(int)((rb+lk2)&31);
          A[lk2*68+lc+0]=sc.x*zi[(lc+0)*32+zr];
          A[lk2*68+lc+1]=sc.y*zi[(lc+1)*32+zr];
          A[lk2*68+lc+2]=sc.z*zi[(lc+2)*32+zr];
          A[lk2*68+lc+3]=sc.w*zi[(lc+3)*32+zr];
          float4 mv=*(const float4*)(g_mem+(rb+lk2)*HH+h0+lc);
          *(float4*)&B[lk2*68+lc]=mv;
          __syncthreads();
          #pragma unroll
          for(int k=0;k<16;k++){
            float4 af=*(const float4*)&A[k*68+ty*4];
            float4 bf4=*(const float4*)&B[k*68+tx*4];
            float av[4]={af.x,af.y,af.z,af.w}, bvv[4]={bf4.x,bf4.y,bf4.z,bf4.w};
            #pragma unroll
            for(int i=0;i<4;i++)
              #pragma unroll
              for(int j2=0;j2<4;j2++) acc[i][j2]+=av[i]*bvv[j2];
          }
          __syncthreads();
        }
        #pragma unroll
        for(int i=0;i<4;i++)
          #pragma unroll
          for(int j2=0;j2<4;j2++)
            atomicAdd(&g_V[(size_t)(ty*4+i)*HH+h0+tx*4+j2],acc[i][j2]);
      }
    }
    gbar(1,NB);
    // ---- P5: logits (queue, 250 jobs of 128 v) ; blk295 vts copy
    {
      if(blk==295){
        for(int i=tid;i<16384;i+=256) g_vts[(size_t)s*16384+i]=__ldcg(&g_V[16384+i]);
      }
      float4* s4=(float4*)sh;
      const float4* v4=(const float4*)g_V;
      #pragma unroll
      for(int i=0;i<16;i++) s4[tid+i*256]=__ldcg(v4+tid+i*256);
      __syncthreads();
      unsigned base=(unsigned)s*(J5+NB);
      int vloc=tid>>1, khalf=(tid&1)*256;
      for(;;){
        __syncthreads();
        if(tid==0){ unsigned t=atomicAdd(&g_q[2],1u); sjob=(t<base+J5)?(int)(t-base):-1; }
        __syncthreads();
        int job=sjob; if(job<0) break;
        int v=job*128+vloc;
        float acc[32];
        #pragma unroll
        for(int b=0;b<32;b++) acc[b]=0.f;
        for(int k2=0;k2<64;k2++){
          int k=khalf+k2*4;
          float w0=__ldcg(&g_genT[(size_t)(k+0)*VV+v]);
          float w1=__ldcg(&g_genT[(size_t)(k+1)*VV+v]);
          float w2=__ldcg(&g_genT[(size_t)(k+2)*VV+v]);
          float w3=__ldcg(&g_genT[(size_t)(k+3)*VV+v]);
          #pragma unroll
          for(int b=0;b<32;b++){
            float4 x=*(const float4*)(sh+b*HH+k);
            acc[b]+=w0*x.x+w1*x.y+w2*x.z+w3*x.w;
          }
        }
        #pragma unroll
        for(int b=0;b<32;b++) acc[b]+=__shfl_xor_sync(0xffffffffu,acc[b],1);
        if(!(tid&1)){
          float bb2=genb[v];
          #pragma unroll
          for(int b=0;b<32;b++) g_logits[(size_t)b*VV+v]=acc[b]+bb2;
        }
      }
    }
    gbar(1,NB);
    // ---- P6: lse + argmax (0..31)
    if(blk<32){
      float* mx=red; float* ss=red+256; int* ii=(int*)(red+512);
      const float* lg=g_logits+(size_t)blk*VV;
      float m=-1e30f,sum=0.f; int idx=0;
      for(int v=tid;v<VV;v+=256){
        float l=__ldcg(&lg[v]);
        if(l>m){ sum=sum*expf(m-l)+1.f; m=l; idx=v; }
        else sum+=expf(l-m);
      }
      mx[tid]=m; ss[tid]=sum; ii[tid]=idx;
      __syncthreads();
      for(int o=128;o;o>>=1){
        if(tid<o){
          float m1=mx[tid],m2=mx[tid+o],s1=ss[tid],s2=ss[tid+o];
          int i1=ii[tid],i2=ii[tid+o];
          float M=fmaxf(m1,m2);
          ss[tid]=s1*expf(m1-M)+s2*expf(m2-M);
          mx[tid]=M;
          ii[tid]=(m2>m1)?i2:(m1>m2?i1:min(i1,i2));
        }
        __syncthreads();
      }
      if(tid==0){ g_lse[blk]=mx[0]+logf(ss[0]); g_w[blk]=ii[0]; }
    }
    gbar(1,NB);
  }
  // tail: writeback s=63
  for(unsigned idx=blk*256+tid; idx<1024000u; idx+=(unsigned)NB*256){
    unsigned b=idx/32000u, v=idx-b*32000u;
    out[((size_t)b*64+63)*VV+v]=__ldcg(&g_logits[(size_t)b*VV+v])-__ldcg(&g_lse[b]);
  }
}

__global__ void k_cls(const float* __restrict__ W, const float* __restrict__ cb,
                      float* __restrict__ out){
  __shared__ float rr[256];
  int b=blockIdx.x, l=blockIdx.y, tid=threadIdx.x;
  const float* wr=W+(size_t)l*237568;
  float acc=0.f;
  for(int k=tid;k<32768;k+=256)
    acc+=wr[k]*g_vts[(size_t)(k>>9)*16384+b*HH+(k&511)];
  for(int k=32768+tid;k<237568;k+=256){
    int kk=k-32768;
    acc+=wr[k]*g_mem[((size_t)(kk>>9)*32+b)*HH+(kk&511)];
  }
  rr[tid]=acc;
  __syncthreads();
  for(int o=128;o;o>>=1){ if(tid<o) rr[tid]+=rr[tid+o]; __syncthreads(); }
  if(tid==0) out[65536000u+b*5+l]=rr[0]+cb[l];
}

extern "C" void kernel_launch(void* const* d_in, const int* in_sizes, int n_in,
                              void* d_out, int out_size){
  const int*   orig=(const int*)  d_in[0];
  const float* emb =(const float*)d_in[1];
  const float* eWif=(const float*)d_in[2];
  const float* eWhf=(const float*)d_in[3];
  const float* ebf =(const float*)d_in[4];
  const float* eWib=(const float*)d_in[5];
  const float* eWhb=(const float*)d_in[6];
  const float* ebb =(const float*)d_in[7];
  const float* dWi =(const float*)d_in[8];
  const float* dWh =(const float*)d_in[9];
  const float* db  =(const float*)d_in[10];
  const float* sAw =(const float*)d_in[11];
  const float* cAw =(const float*)d_in[12];
  const float* gW  =(const float*)d_in[13];
  const float* gb  =(const float*)d_in[14];
  const float* cW  =(const float*)d_in[15];
  const float* cb  =(const float*)d_in[16];
  float* out=(float*)d_out;

  cudaFuncSetAttribute(k_enc, cudaFuncAttributeMaxDynamicSharedMemorySize, 103424);
  cudaFuncSetAttribute(k_dec, cudaFuncAttributeMaxDynamicSharedMemorySize, 99328);

  k_prep<<<256,256>>>();
  k_tr_all<<<20608,dim3(32,8)>>>(eWhf, eWhb, dWi, dWh, sAw, cAw, gW);
  k_xpre<<<dim3(100,32,2),256>>>(orig, emb, eWif, ebf, eWib, ebb);
  k_enc<<<256,256,103424>>>();
  k_dinit<<<25600,256>>>();
  k_dec<<<NB,256,99328>>>(emb, db, gb, out);
  k_cls<<<dim3(32,5),256>>>(cW, cb, out);
}